// round 1
// baseline (speedup 1.0000x reference)
#include <cuda_runtime.h>
#include <math.h>

#define B_  2
#define L_  2048
#define D_  1024
#define H_  16
#define HD_ 64
#define M_  (B_*L_)   // 4096

// Scratch (device globals — no allocation allowed)
__device__ float g_q[B_*H_*L_*HD_];
__device__ float g_k[B_*H_*L_*HD_];
__device__ float g_v[B_*H_*L_*HD_];
__device__ float g_ctx[B_*L_*D_];

// ---------------------------------------------------------------------------
// C[M,N] = X[M,K] @ W[N,K]^T  (+bias), K = N = 1024, M = 4096.
// 64x64 block tile, 256 threads, 4x4 per-thread microtile, BK=16.
// SPLIT: write output in [B,H,L,hd] layout (fused split_heads).
// ---------------------------------------------------------------------------
template<bool SPLIT, bool BIAS>
__global__ __launch_bounds__(256) void gemm_xwT(const float* __restrict__ X,
                                                const float* __restrict__ W,
                                                const float* __restrict__ bias,
                                                float* __restrict__ out)
{
    __shared__ float As[64][17];
    __shared__ float Bs[64][17];
    const int tid = threadIdx.x;
    const int tx = tid & 15, ty = tid >> 4;
    const int m0 = blockIdx.y * 64, n0 = blockIdx.x * 64;

    float acc[4][4] = {};

    const int r  = tid >> 2;
    const int c4 = (tid & 3) * 4;

    for (int k0 = 0; k0 < D_; k0 += 16) {
        const float4 av = *(const float4*)&X[(size_t)(m0 + r) * D_ + k0 + c4];
        const float4 bv = *(const float4*)&W[(size_t)(n0 + r) * D_ + k0 + c4];
        As[r][c4+0] = av.x; As[r][c4+1] = av.y; As[r][c4+2] = av.z; As[r][c4+3] = av.w;
        Bs[r][c4+0] = bv.x; Bs[r][c4+1] = bv.y; Bs[r][c4+2] = bv.z; Bs[r][c4+3] = bv.w;
        __syncthreads();

        #pragma unroll
        for (int kk = 0; kk < 16; kk++) {
            float a[4], b[4];
            #pragma unroll
            for (int i = 0; i < 4; i++) a[i] = As[ty*4+i][kk];
            #pragma unroll
            for (int j = 0; j < 4; j++) b[j] = Bs[tx*4+j][kk];
            #pragma unroll
            for (int i = 0; i < 4; i++)
                #pragma unroll
                for (int j = 0; j < 4; j++)
                    acc[i][j] = fmaf(a[i], b[j], acc[i][j]);
        }
        __syncthreads();
    }

    #pragma unroll
    for (int i = 0; i < 4; i++) {
        const int m = m0 + ty*4 + i;
        #pragma unroll
        for (int j = 0; j < 4; j++) {
            const int n = n0 + tx*4 + j;
            float v = acc[i][j];
            if (BIAS) v += bias[n];
            if (SPLIT) {
                const int b = m / L_, l = m % L_, h = n / HD_, d = n % HD_;
                out[(((size_t)(b*H_ + h))*L_ + l)*HD_ + d] = v;
            } else {
                out[(size_t)m * D_ + n] = v;
            }
        }
    }
}

// ---------------------------------------------------------------------------
// Flash attention: 1 CTA per (b*H+h, 64-query tile). Online softmax over
// 64-key tiles. Mask: key with mask==0 gets probability exactly 0.
// smem: Qs,Ks,Vs,Ss [64][65] fp32 + m/l/corr[64] + msk[64]
// ---------------------------------------------------------------------------
#define ATT_SMEM ((4*64*65 + 3*64) * 4 + 64 * 4)   // 67584 bytes

__global__ __launch_bounds__(256) void flash_attn(const float* __restrict__ q,
                                                  const float* __restrict__ k,
                                                  const float* __restrict__ v,
                                                  const int*   __restrict__ mask,
                                                  float* __restrict__ ctx)
{
    extern __shared__ float sm[];
    float* Qs   = sm;              // 64*65
    float* Ks   = Qs + 64*65;
    float* Vs   = Ks + 64*65;
    float* Ss   = Vs + 64*65;
    float* m_s  = Ss + 64*65;      // 64
    float* l_s  = m_s + 64;        // 64
    float* corr = l_s + 64;        // 64
    int*   msk  = (int*)(corr + 64);

    const int bh = blockIdx.x;         // b*H + h
    const int b  = bh / H_;
    const int h  = bh % H_;
    const int q0 = blockIdx.y * 64;
    const int tid = threadIdx.x;
    const int tx = tid & 15, ty = tid >> 4;

    const float* qbase = q + (size_t)bh * L_ * HD_;
    const float* kbase = k + (size_t)bh * L_ * HD_;
    const float* vbase = v + (size_t)bh * L_ * HD_;

    // Load Q tile (64 rows x 64 dims), vectorized
    {
        const int rr = tid >> 2;            // 0..63
        const int cc = (tid & 3) * 16;      // 0,16,32,48
        #pragma unroll
        for (int u = 0; u < 4; u++) {
            const float4 qv = *(const float4*)&qbase[(size_t)(q0 + rr)*HD_ + cc + u*4];
            Qs[rr*65 + cc + u*4 + 0] = qv.x;
            Qs[rr*65 + cc + u*4 + 1] = qv.y;
            Qs[rr*65 + cc + u*4 + 2] = qv.z;
            Qs[rr*65 + cc + u*4 + 3] = qv.w;
        }
    }
    if (tid < 64) { m_s[tid] = -1e30f; l_s[tid] = 0.f; }

    float acc[4][4] = {};
    __syncthreads();

    for (int k0 = 0; k0 < L_; k0 += 64) {
        // Load K,V tiles + mask
        {
            const int rr = tid >> 2;
            const int cc = (tid & 3) * 16;
            #pragma unroll
            for (int u = 0; u < 4; u++) {
                const float4 kv = *(const float4*)&kbase[(size_t)(k0 + rr)*HD_ + cc + u*4];
                const float4 vv = *(const float4*)&vbase[(size_t)(k0 + rr)*HD_ + cc + u*4];
                Ks[rr*65 + cc + u*4 + 0] = kv.x;
                Ks[rr*65 + cc + u*4 + 1] = kv.y;
                Ks[rr*65 + cc + u*4 + 2] = kv.z;
                Ks[rr*65 + cc + u*4 + 3] = kv.w;
                Vs[rr*65 + cc + u*4 + 0] = vv.x;
                Vs[rr*65 + cc + u*4 + 1] = vv.y;
                Vs[rr*65 + cc + u*4 + 2] = vv.z;
                Vs[rr*65 + cc + u*4 + 3] = vv.w;
            }
        }
        if (tid < 64) msk[tid] = mask[b*L_ + k0 + tid];
        __syncthreads();

        // S = (Q K^T) / 8, mask -> -1e30
        float s[4][4] = {};
        #pragma unroll 4
        for (int dd = 0; dd < 64; dd++) {
            float a[4], bb[4];
            #pragma unroll
            for (int i = 0; i < 4; i++) a[i]  = Qs[(ty*4+i)*65 + dd];
            #pragma unroll
            for (int j = 0; j < 4; j++) bb[j] = Ks[(tx*4+j)*65 + dd];
            #pragma unroll
            for (int i = 0; i < 4; i++)
                #pragma unroll
                for (int j = 0; j < 4; j++)
                    s[i][j] = fmaf(a[i], bb[j], s[i][j]);
        }
        #pragma unroll
        for (int j = 0; j < 4; j++) {
            const bool keep = (msk[tx*4+j] != 0);
            #pragma unroll
            for (int i = 0; i < 4; i++)
                Ss[(ty*4+i)*65 + tx*4+j] = keep ? s[i][j] * 0.125f : -1e30f;
        }
        __syncthreads();

        // Online-softmax row update: one thread per query row
        if (tid < 64) {
            const float mo = m_s[tid];
            float rmax = mo;
            #pragma unroll 8
            for (int kk = 0; kk < 64; kk++) rmax = fmaxf(rmax, Ss[tid*65 + kk]);
            const float c_ = __expf(mo - rmax);   // both -1e30 -> exp(0)=1, l stays 0
            float ls = 0.f;
            #pragma unroll 8
            for (int kk = 0; kk < 64; kk++) {
                const float sv = Ss[tid*65 + kk];
                const float p = (sv < -1e29f) ? 0.f : __expf(sv - rmax);
                Ss[tid*65 + kk] = p;
                ls += p;
            }
            m_s[tid]  = rmax;
            l_s[tid]  = l_s[tid] * c_ + ls;
            corr[tid] = c_;
        }
        __syncthreads();

        // acc = acc*corr + P @ V
        #pragma unroll
        for (int i = 0; i < 4; i++) {
            const float c_ = corr[ty*4+i];
            #pragma unroll
            for (int j = 0; j < 4; j++) acc[i][j] *= c_;
        }
        #pragma unroll 4
        for (int kk = 0; kk < 64; kk++) {
            float p[4], vv[4];
            #pragma unroll
            for (int i = 0; i < 4; i++) p[i]  = Ss[(ty*4+i)*65 + kk];
            #pragma unroll
            for (int j = 0; j < 4; j++) vv[j] = Vs[kk*65 + tx*4+j];
            #pragma unroll
            for (int i = 0; i < 4; i++)
                #pragma unroll
                for (int j = 0; j < 4; j++)
                    acc[i][j] = fmaf(p[i], vv[j], acc[i][j]);
        }
        __syncthreads();
    }

    // Normalize and write ctx in [B,L,D] combined-head layout
    #pragma unroll
    for (int i = 0; i < 4; i++) {
        const int l = q0 + ty*4 + i;
        const float lv = l_s[ty*4+i];
        const float inv = (lv > 0.f) ? 1.f / lv : 0.f;  // fully-masked row -> 0 (matches NaN->0)
        #pragma unroll
        for (int j = 0; j < 4; j++)
            ctx[((size_t)(b*L_ + l))*D_ + h*HD_ + tx*4 + j] = acc[i][j] * inv;
    }
}

// ---------------------------------------------------------------------------
extern "C" void kernel_launch(void* const* d_in, const int* in_sizes, int n_in,
                              void* d_out, int out_size)
{
    const float* query = (const float*)d_in[0];
    const float* key_  = (const float*)d_in[1];
    const float* value = (const float*)d_in[2];
    const int*   mask  = (const int*)  d_in[3];
    const float* Wq    = (const float*)d_in[4];
    const float* Wk    = (const float*)d_in[5];
    const float* Wv    = (const float*)d_in[6];
    const float* Wo    = (const float*)d_in[7];
    const float* bo    = (const float*)d_in[8];
    float* out = (float*)d_out;

    float *pq, *pk, *pv, *pc;
    cudaGetSymbolAddress((void**)&pq, g_q);
    cudaGetSymbolAddress((void**)&pk, g_k);
    cudaGetSymbolAddress((void**)&pv, g_v);
    cudaGetSymbolAddress((void**)&pc, g_ctx);

    const dim3 gg(D_/64, M_/64);   // (16, 64)

    gemm_xwT<true,  false><<<gg, 256>>>(query, Wq, nullptr, pq);
    gemm_xwT<true,  false><<<gg, 256>>>(key_,  Wk, nullptr, pk);
    gemm_xwT<true,  false><<<gg, 256>>>(value, Wv, nullptr, pv);

    cudaFuncSetAttribute(flash_attn, cudaFuncAttributeMaxDynamicSharedMemorySize, ATT_SMEM);
    flash_attn<<<dim3(B_*H_, L_/64), 256, ATT_SMEM>>>(pq, pk, pv, mask, pc);

    gemm_xwT<false, true><<<gg, 256>>>(pc, Wo, bo, out);
}

// round 5
// speedup vs baseline: 2.5083x; 2.5083x over previous
#include <cuda_runtime.h>
#include <math.h>
#include <stdint.h>

#define B_  2
#define L_  2048
#define D_  1024
#define H_  16
#define HD_ 64
#define M_  (B_*L_)   // 4096

// Scratch (device globals — no allocation allowed)
__device__ float g_q[B_*H_*L_*HD_];
__device__ float g_k[B_*H_*L_*HD_];
__device__ float g_v[B_*H_*L_*HD_];
__device__ float g_ctx[B_*L_*D_];

// ---------------------------------------------------------------------------
// helpers
// ---------------------------------------------------------------------------
__device__ __forceinline__ uint32_t f2tf(float f) {
    uint32_t r;
    asm("cvt.rna.tf32.f32 %0, %1;" : "=r"(r) : "f"(f));
    return r;
}
// D += A*B, m16n8k8 tf32 (A row-major, B col-major i.e. B[k][n] indexed [n][k])
__device__ __forceinline__ void mma8(float* d, const uint32_t* a, const uint32_t* b) {
    asm volatile(
        "mma.sync.aligned.m16n8k8.row.col.f32.tf32.tf32.f32 "
        "{%0,%1,%2,%3}, {%4,%5,%6,%7}, {%8,%9}, {%0,%1,%2,%3};"
        : "+f"(d[0]), "+f"(d[1]), "+f"(d[2]), "+f"(d[3])
        : "r"(a[0]), "r"(a[1]), "r"(a[2]), "r"(a[3]), "r"(b[0]), "r"(b[1]));
}

// ===========================================================================
// GEMM: C[M,N] = X[M,K] @ W[N,K]^T (+bias), K=N=1024.
// 128x128 CTA tile, 256 thr (8 warps, 2x4), warp tile 64x32, K-chunk 32.
// smem stride 36 words -> fragment LDS patterns conflict-free.
// ===========================================================================
template<bool SPLIT, bool BIAS>
__global__ __launch_bounds__(256, 2) void gemm_tc(const float* __restrict__ X,
                                                  const float* __restrict__ W,
                                                  const float* __restrict__ bias,
                                                  float* __restrict__ out)
{
    __shared__ uint32_t As[128 * 36];
    __shared__ uint32_t Bs[128 * 36];

    const int tid  = threadIdx.x;
    const int wid  = tid >> 5, lane = tid & 31;
    const int qd   = lane & 3, gr = lane >> 2;
    const int wm   = wid >> 2, wn = wid & 3;         // 2 x 4 warp grid
    const int m0   = blockIdx.y * 128, n0 = blockIdx.x * 128;

    float acc[4][4][4];
    #pragma unroll
    for (int a = 0; a < 4; a++)
        #pragma unroll
        for (int b = 0; b < 4; b++)
            #pragma unroll
            for (int c = 0; c < 4; c++) acc[a][b][c] = 0.f;

    const int lrow = tid >> 1;            // 0..127
    const int lcol = (tid & 1) * 16;      // 0 / 16
    const float* Xp = X + (size_t)(m0 + lrow) * D_ + lcol;
    const float* Wp = W + (size_t)(n0 + lrow) * D_ + lcol;
    uint32_t* Ast = As + lrow * 36 + lcol;
    uint32_t* Bst = Bs + lrow * 36 + lcol;

    for (int c = 0; c < D_; c += 32) {
        #pragma unroll
        for (int u = 0; u < 4; u++) {
            const float4 xa = *(const float4*)(Xp + c + u * 4);
            const float4 wb = *(const float4*)(Wp + c + u * 4);
            uint4 ta, tb;
            ta.x = f2tf(xa.x); ta.y = f2tf(xa.y); ta.z = f2tf(xa.z); ta.w = f2tf(xa.w);
            tb.x = f2tf(wb.x); tb.y = f2tf(wb.y); tb.z = f2tf(wb.z); tb.w = f2tf(wb.w);
            *(uint4*)(Ast + u * 4) = ta;
            *(uint4*)(Bst + u * 4) = tb;
        }
        __syncthreads();

        #pragma unroll
        for (int kk = 0; kk < 32; kk += 8) {
            uint32_t af[4][4], bf[4][2];
            #pragma unroll
            for (int mt = 0; mt < 4; mt++) {
                const uint32_t* p = As + (wm * 64 + mt * 16 + gr) * 36 + kk + qd;
                af[mt][0] = p[0];
                af[mt][1] = p[8 * 36];
                af[mt][2] = p[4];
                af[mt][3] = p[8 * 36 + 4];
            }
            #pragma unroll
            for (int nt = 0; nt < 4; nt++) {
                const uint32_t* p = Bs + (wn * 32 + nt * 8 + gr) * 36 + kk + qd;
                bf[nt][0] = p[0];
                bf[nt][1] = p[4];
            }
            #pragma unroll
            for (int mt = 0; mt < 4; mt++)
                #pragma unroll
                for (int nt = 0; nt < 4; nt++)
                    mma8(acc[mt][nt], af[mt], bf[nt]);
        }
        __syncthreads();
    }

    // epilogue: c0,c1 -> (row gr, cols 2qd,2qd+1); c2,c3 -> row gr+8
    #pragma unroll
    for (int mt = 0; mt < 4; mt++) {
        #pragma unroll
        for (int half = 0; half < 2; half++) {
            const int m = m0 + wm * 64 + mt * 16 + gr + half * 8;
            #pragma unroll
            for (int nt = 0; nt < 4; nt++) {
                const int n = n0 + wn * 32 + nt * 8 + qd * 2;
                float2 v;
                v.x = acc[mt][nt][half * 2 + 0];
                v.y = acc[mt][nt][half * 2 + 1];
                if (BIAS) { v.x += bias[n]; v.y += bias[n + 1]; }
                if (SPLIT) {
                    const int b = m / L_, l = m % L_, h = n / HD_, d = n % HD_;
                    *(float2*)&out[(((size_t)(b * H_ + h)) * L_ + l) * HD_ + d] = v;
                } else {
                    *(float2*)&out[(size_t)m * D_ + n] = v;
                }
            }
        }
    }
}

// ===========================================================================
// Flash attention with mma.sync tf32.
// CTA = (b*H+h, 64-query tile), 256 thr (8 warps 4x2), warp tile 16x32.
// smem word-offsets: Qs/Ks stride 68, Vs stride 72, Ps stride 68.
// ===========================================================================
#define QS_OFF 0
#define KS_OFF (64 * 68)
#define VS_OFF (KS_OFF + 64 * 68)
#define PS_OFF (VS_OFF + 64 * 72)
#define MS_OFF (PS_OFF + 64 * 68)
#define LS_OFF (MS_OFF + 64)
#define CR_OFF (LS_OFF + 64)
#define MK_OFF (CR_OFF + 64)
#define ATT_SMEM ((MK_OFF + 64) * 4)   // 71680 bytes

__global__ __launch_bounds__(256) void flash_attn(const float* __restrict__ q,
                                                  const float* __restrict__ k,
                                                  const float* __restrict__ v,
                                                  const int*   __restrict__ mask,
                                                  float* __restrict__ ctx)
{
    extern __shared__ uint32_t smu[];
    uint32_t* Qs  = smu + QS_OFF;
    uint32_t* Ks  = smu + KS_OFF;
    uint32_t* Vs  = smu + VS_OFF;
    float*    Psf = (float*)(smu + PS_OFF);
    uint32_t* Psu = smu + PS_OFF;
    float*    m_s = (float*)(smu + MS_OFF);
    float*    l_s = (float*)(smu + LS_OFF);
    float*    crr = (float*)(smu + CR_OFF);
    int*      msk = (int*)(smu + MK_OFF);

    const int bh = blockIdx.x;
    const int b  = bh / H_;
    const int h  = bh % H_;
    const int q0 = blockIdx.y * 64;
    const int tid  = threadIdx.x;
    const int wid  = tid >> 5, lane = tid & 31;
    const int qd   = lane & 3, gr = lane >> 2;
    const int wm   = wid >> 1, wn = wid & 1;     // 4 x 2 warp grid

    const float* qbase = q + (size_t)bh * L_ * HD_;
    const float* kbase = k + (size_t)bh * L_ * HD_;
    const float* vbase = v + (size_t)bh * L_ * HD_;

    // Load Q tile (scaled by 1/8, tf32)
    {
        const int rr = tid >> 2;
        const int cc = (tid & 3) * 16;
        #pragma unroll
        for (int u = 0; u < 4; u++) {
            const float4 qv = *(const float4*)&qbase[(size_t)(q0 + rr) * HD_ + cc + u * 4];
            uint4 t;
            t.x = f2tf(qv.x * 0.125f); t.y = f2tf(qv.y * 0.125f);
            t.z = f2tf(qv.z * 0.125f); t.w = f2tf(qv.w * 0.125f);
            *(uint4*)(Qs + rr * 68 + cc + u * 4) = t;
        }
    }
    if (tid < 64) { m_s[tid] = -1e30f; l_s[tid] = 0.f; }

    float accO[4][4];
    #pragma unroll
    for (int a = 0; a < 4; a++)
        #pragma unroll
        for (int c = 0; c < 4; c++) accO[a][c] = 0.f;

    const int r0 = wm * 16 + gr;   // this thread's upper S/O row
    __syncthreads();

    for (int k0 = 0; k0 < L_; k0 += 64) {
        // Load K (stride 68) and V (stride 72) tiles, tf32
        {
            const int rr = tid >> 2;
            const int cc = (tid & 3) * 16;
            #pragma unroll
            for (int u = 0; u < 4; u++) {
                const float4 kv = *(const float4*)&kbase[(size_t)(k0 + rr) * HD_ + cc + u * 4];
                const float4 vv = *(const float4*)&vbase[(size_t)(k0 + rr) * HD_ + cc + u * 4];
                uint4 tk, tv;
                tk.x = f2tf(kv.x); tk.y = f2tf(kv.y); tk.z = f2tf(kv.z); tk.w = f2tf(kv.w);
                tv.x = f2tf(vv.x); tv.y = f2tf(vv.y); tv.z = f2tf(vv.z); tv.w = f2tf(vv.w);
                *(uint4*)(Ks + rr * 68 + cc + u * 4) = tk;
                *(uint4*)(Vs + rr * 72 + cc + u * 4) = tv;
            }
        }
        if (tid < 64) msk[tid] = mask[b * L_ + k0 + tid];
        __syncthreads();

        // S = Q*K^T (scale already in Q)
        float sacc[4][4];
        #pragma unroll
        for (int a = 0; a < 4; a++)
            #pragma unroll
            for (int c = 0; c < 4; c++) sacc[a][c] = 0.f;

        #pragma unroll
        for (int kk = 0; kk < 64; kk += 8) {
            uint32_t af[4], bf[4][2];
            {
                const uint32_t* p = Qs + r0 * 68 + kk + qd;
                af[0] = p[0]; af[1] = p[8 * 68]; af[2] = p[4]; af[3] = p[8 * 68 + 4];
            }
            #pragma unroll
            for (int nt = 0; nt < 4; nt++) {
                const uint32_t* p = Ks + (wn * 32 + nt * 8 + gr) * 68 + kk + qd;
                bf[nt][0] = p[0]; bf[nt][1] = p[4];
            }
            #pragma unroll
            for (int nt = 0; nt < 4; nt++) mma8(sacc[nt], af, bf[nt]);
        }

        // write masked S to Ps
        #pragma unroll
        for (int nt = 0; nt < 4; nt++) {
            const int n = wn * 32 + nt * 8 + qd * 2;
            const bool k0ok = (msk[n] != 0), k1ok = (msk[n + 1] != 0);
            float* pr = Psf + r0 * 68 + n;
            pr[0]          = k0ok ? sacc[nt][0] : -1e30f;
            pr[1]          = k1ok ? sacc[nt][1] : -1e30f;
            pr[8 * 68]     = k0ok ? sacc[nt][2] : -1e30f;
            pr[8 * 68 + 1] = k1ok ? sacc[nt][3] : -1e30f;
        }
        __syncthreads();

        // online softmax: quad per row, 16 cols per thread
        {
            const int row = tid >> 2, q4 = tid & 3;
            float* pr = Psf + row * 68 + q4 * 16;
            const float mo = m_s[row];
            float rmax = mo;
            #pragma unroll
            for (int j = 0; j < 16; j++) rmax = fmaxf(rmax, pr[j]);
            rmax = fmaxf(rmax, __shfl_xor_sync(0xFFFFFFFF, rmax, 1));
            rmax = fmaxf(rmax, __shfl_xor_sync(0xFFFFFFFF, rmax, 2));
            float ls = 0.f;
            #pragma unroll
            for (int j = 0; j < 16; j++) {
                const float sv = pr[j];
                const float p = (sv < -1e29f) ? 0.f : __expf(sv - rmax);
                ((uint32_t*)pr)[j] = f2tf(p);
                ls += p;
            }
            ls += __shfl_xor_sync(0xFFFFFFFF, ls, 1);
            ls += __shfl_xor_sync(0xFFFFFFFF, ls, 2);
            if (q4 == 0) {
                const float c_ = __expf(mo - rmax);
                m_s[row] = rmax;
                l_s[row] = l_s[row] * c_ + ls;
                crr[row] = c_;
            }
        }
        __syncthreads();

        // acc = acc*corr + P @ V
        {
            const float c0 = crr[r0], c1 = crr[r0 + 8];
            #pragma unroll
            for (int nt = 0; nt < 4; nt++) {
                accO[nt][0] *= c0; accO[nt][1] *= c0;
                accO[nt][2] *= c1; accO[nt][3] *= c1;
            }
        }
        #pragma unroll
        for (int kk = 0; kk < 64; kk += 8) {
            uint32_t af[4], bf[4][2];
            {
                const uint32_t* p = Psu + r0 * 68 + kk + qd;
                af[0] = p[0]; af[1] = p[8 * 68]; af[2] = p[4]; af[3] = p[8 * 68 + 4];
            }
            #pragma unroll
            for (int nt = 0; nt < 4; nt++) {
                const uint32_t* p = Vs + (kk + qd) * 72 + wn * 32 + nt * 8 + gr;
                bf[nt][0] = p[0];
                bf[nt][1] = p[4 * 72];
            }
            #pragma unroll
            for (int nt = 0; nt < 4; nt++) mma8(accO[nt], af, bf[nt]);
        }
        __syncthreads();
    }

    // normalize + write ctx
    {
        const float l0 = l_s[r0], l1 = l_s[r0 + 8];
        const float i0 = (l0 > 0.f) ? 1.f / l0 : 0.f;
        const float i1 = (l1 > 0.f) ? 1.f / l1 : 0.f;
        #pragma unroll
        for (int nt = 0; nt < 4; nt++) {
            const int n = wn * 32 + nt * 8 + qd * 2;
            float2 v0, v1;
            v0.x = accO[nt][0] * i0; v0.y = accO[nt][1] * i0;
            v1.x = accO[nt][2] * i1; v1.y = accO[nt][3] * i1;
            *(float2*)&ctx[((size_t)(b * L_ + q0 + r0)) * D_ + h * HD_ + n] = v0;
            *(float2*)&ctx[((size_t)(b * L_ + q0 + r0 + 8)) * D_ + h * HD_ + n] = v1;
        }
    }
}

// ---------------------------------------------------------------------------
extern "C" void kernel_launch(void* const* d_in, const int* in_sizes, int n_in,
                              void* d_out, int out_size)
{
    const float* query = (const float*)d_in[0];
    const float* key_  = (const float*)d_in[1];
    const float* value = (const float*)d_in[2];
    const int*   mask  = (const int*)  d_in[3];
    const float* Wq    = (const float*)d_in[4];
    const float* Wk    = (const float*)d_in[5];
    const float* Wv    = (const float*)d_in[6];
    const float* Wo    = (const float*)d_in[7];
    const float* bo    = (const float*)d_in[8];
    float* out = (float*)d_out;

    float *pq, *pk, *pv, *pc;
    cudaGetSymbolAddress((void**)&pq, g_q);
    cudaGetSymbolAddress((void**)&pk, g_k);
    cudaGetSymbolAddress((void**)&pv, g_v);
    cudaGetSymbolAddress((void**)&pc, g_ctx);

    const dim3 gg(D_ / 128, M_ / 128);   // (8, 32)

    gemm_tc<true,  false><<<gg, 256>>>(query, Wq, nullptr, pq);
    gemm_tc<true,  false><<<gg, 256>>>(key_,  Wk, nullptr, pk);
    gemm_tc<true,  false><<<gg, 256>>>(value, Wv, nullptr, pv);

    cudaFuncSetAttribute(flash_attn, cudaFuncAttributeMaxDynamicSharedMemorySize, ATT_SMEM);
    flash_attn<<<dim3(B_ * H_, L_ / 64), 256, ATT_SMEM>>>(pq, pk, pv, mask, pc);

    gemm_tc<false, true><<<gg, 256>>>(pc, Wo, bo, out);
}

// round 6
// speedup vs baseline: 3.1303x; 1.2480x over previous
#include <cuda_runtime.h>
#include <math.h>
#include <stdint.h>

#define B_  2
#define L_  2048
#define D_  1024
#define H_  16
#define HD_ 64
#define M_  (B_*L_)   // 4096

// Scratch (device globals — no allocation allowed)
__device__ float g_q[B_*H_*L_*HD_];
__device__ float g_k[B_*H_*L_*HD_];
__device__ float g_v[B_*H_*L_*HD_];
__device__ float g_ctx[B_*L_*D_];

// ---------------------------------------------------------------------------
// helpers
// ---------------------------------------------------------------------------
__device__ __forceinline__ uint32_t f2tf(float f) {
    uint32_t r;
    asm("cvt.rna.tf32.f32 %0, %1;" : "=r"(r) : "f"(f));
    return r;
}
__device__ __forceinline__ uint32_t smem_u32(const void* p) {
    uint32_t a;
    asm("{ .reg .u64 t; cvta.to.shared.u64 t, %1; cvt.u32.u64 %0, t; }"
        : "=r"(a) : "l"(p));
    return a;
}
__device__ __forceinline__ void cp16(uint32_t s, const void* g) {
    asm volatile("cp.async.cg.shared.global [%0], [%1], 16;" :: "r"(s), "l"(g));
}
// D += A*B, m16n8k8 tf32 (A row-major, B col-major)
__device__ __forceinline__ void mma8(float* d, const uint32_t* a, const uint32_t* b) {
    asm volatile(
        "mma.sync.aligned.m16n8k8.row.col.f32.tf32.tf32.f32 "
        "{%0,%1,%2,%3}, {%4,%5,%6,%7}, {%8,%9}, {%0,%1,%2,%3};"
        : "+f"(d[0]), "+f"(d[1]), "+f"(d[2]), "+f"(d[3])
        : "r"(a[0]), "r"(a[1]), "r"(a[2]), "r"(a[3]), "r"(b[0]), "r"(b[1]));
}

// ===========================================================================
// GEMM: C[M,N] = X[M,K] @ W[N,K]^T (+bias), K=N=1024.
// 128x128 CTA tile, 256 thr (8 warps 2x4), warp tile 64x32, K-chunk 32.
// cp.async double-buffered smem (raw fp32; tf32 cvt at fragment load).
// smem stride 36 words -> all fragment LDS conflict-free.
// ===========================================================================
#define GST (128 * 36)           // words per operand per stage
#define GEMM_SMEM (4 * GST * 4)  // 2 stages x (A+B) = 73728 bytes

template<bool SPLIT, bool BIAS>
__global__ __launch_bounds__(256, 2) void gemm_tc(const float* __restrict__ X,
                                                  const float* __restrict__ W,
                                                  const float* __restrict__ bias,
                                                  float* __restrict__ out)
{
    extern __shared__ uint32_t dsm[];   // [stage][A | B]

    const int tid  = threadIdx.x;
    const int wid  = tid >> 5, lane = tid & 31;
    const int qd   = lane & 3, gr = lane >> 2;
    const int wm   = wid >> 2, wn = wid & 3;
    const int m0   = blockIdx.y * 128, n0 = blockIdx.x * 128;

    float acc[4][4][4];
    #pragma unroll
    for (int a = 0; a < 4; a++)
        #pragma unroll
        for (int b = 0; b < 4; b++)
            #pragma unroll
            for (int c = 0; c < 4; c++) acc[a][b][c] = 0.f;

    const int lrow = tid >> 1;            // 0..127
    const int lcol = (tid & 1) * 16;      // 0 / 16
    const float* Xp = X + (size_t)(m0 + lrow) * D_ + lcol;
    const float* Wp = W + (size_t)(n0 + lrow) * D_ + lcol;
    const uint32_t sAb0 = smem_u32(dsm + lrow * 36 + lcol);

    // issue chunk c into stage st
    auto issue = [&](int c, int st) {
        const uint32_t sa = sAb0 + st * (2 * GST * 4);
        const uint32_t sb = sa + GST * 4;
        #pragma unroll
        for (int u = 0; u < 4; u++) {
            cp16(sa + u * 16, Xp + c + u * 4);
            cp16(sb + u * 16, Wp + c + u * 4);
        }
        asm volatile("cp.async.commit_group;");
    };

    issue(0, 0);

    for (int c = 0, st = 0; c < D_; c += 32, st ^= 1) {
        if (c + 32 < D_) {
            issue(c + 32, st ^ 1);
            asm volatile("cp.async.wait_group 1;");
        } else {
            asm volatile("cp.async.wait_group 0;");
        }
        __syncthreads();

        const uint32_t* As = dsm + st * 2 * GST;
        const uint32_t* Bs = As + GST;
        #pragma unroll
        for (int kk = 0; kk < 32; kk += 8) {
            uint32_t af[4][4], bf[4][2];
            #pragma unroll
            for (int mt = 0; mt < 4; mt++) {
                const uint32_t* p = As + (wm * 64 + mt * 16 + gr) * 36 + kk + qd;
                af[mt][0] = f2tf(__uint_as_float(p[0]));
                af[mt][1] = f2tf(__uint_as_float(p[8 * 36]));
                af[mt][2] = f2tf(__uint_as_float(p[4]));
                af[mt][3] = f2tf(__uint_as_float(p[8 * 36 + 4]));
            }
            #pragma unroll
            for (int nt = 0; nt < 4; nt++) {
                const uint32_t* p = Bs + (wn * 32 + nt * 8 + gr) * 36 + kk + qd;
                bf[nt][0] = f2tf(__uint_as_float(p[0]));
                bf[nt][1] = f2tf(__uint_as_float(p[4]));
            }
            #pragma unroll
            for (int mt = 0; mt < 4; mt++)
                #pragma unroll
                for (int nt = 0; nt < 4; nt++)
                    mma8(acc[mt][nt], af[mt], bf[nt]);
        }
        __syncthreads();
    }

    #pragma unroll
    for (int mt = 0; mt < 4; mt++) {
        #pragma unroll
        for (int half = 0; half < 2; half++) {
            const int m = m0 + wm * 64 + mt * 16 + gr + half * 8;
            #pragma unroll
            for (int nt = 0; nt < 4; nt++) {
                const int n = n0 + wn * 32 + nt * 8 + qd * 2;
                float2 v;
                v.x = acc[mt][nt][half * 2 + 0];
                v.y = acc[mt][nt][half * 2 + 1];
                if (BIAS) { v.x += bias[n]; v.y += bias[n + 1]; }
                if (SPLIT) {
                    const int b = m / L_, l = m % L_, h = n / HD_, d = n % HD_;
                    *(float2*)&out[(((size_t)(b * H_ + h)) * L_ + l) * HD_ + d] = v;
                } else {
                    *(float2*)&out[(size_t)m * D_ + n] = v;
                }
            }
        }
    }
}

// ===========================================================================
// Flash attention, FA2-style: q-tile 128, 8 warps, warp tile 16 rows x 64 keys.
// S and softmax stay in registers; P->A-fragment transpose via quad shuffles.
// smem: Qs 128x68 (tf32, pre-scaled), Ks 64x68, Vs 64x72, msk 64.
// ===========================================================================
#define FQS 0
#define FKS (128 * 68)
#define FVS (FKS + 64 * 68)
#define FMK (FVS + 64 * 72)
#define FA_SMEM ((FMK + 64) * 4)   // 70912 bytes

__global__ __launch_bounds__(256, 2) void flash_attn(const float* __restrict__ q,
                                                     const float* __restrict__ k,
                                                     const float* __restrict__ v,
                                                     const int*   __restrict__ mask,
                                                     float* __restrict__ ctx)
{
    extern __shared__ uint32_t smu[];
    uint32_t* Qs  = smu + FQS;
    uint32_t* Ks  = smu + FKS;
    uint32_t* Vs  = smu + FVS;
    int*      msk = (int*)(smu + FMK);

    const int bh = blockIdx.x;
    const int b  = bh / H_;
    const int h  = bh % H_;
    const int q0 = blockIdx.y * 128;
    const int tid  = threadIdx.x;
    const int wid  = tid >> 5, lane = tid & 31;
    const int qd   = lane & 3, gr = lane >> 2;

    const float* qbase = q + (size_t)bh * L_ * HD_;
    const float* kbase = k + (size_t)bh * L_ * HD_;
    const float* vbase = v + (size_t)bh * L_ * HD_;

    // Load Q tile 128x64 (scaled by 1/8, tf32)
    {
        const int rr = tid >> 1;            // 0..127
        const int hc = (tid & 1) * 32;      // 0 / 32
        #pragma unroll
        for (int u = 0; u < 8; u++) {
            const float4 qv = *(const float4*)&qbase[(size_t)(q0 + rr) * HD_ + hc + u * 4];
            uint4 t;
            t.x = f2tf(qv.x * 0.125f); t.y = f2tf(qv.y * 0.125f);
            t.z = f2tf(qv.z * 0.125f); t.w = f2tf(qv.w * 0.125f);
            *(uint4*)(Qs + rr * 68 + hc + u * 4) = t;
        }
    }

    float accO[8][4];
    #pragma unroll
    for (int a = 0; a < 8; a++)
        #pragma unroll
        for (int c = 0; c < 4; c++) accO[a][c] = 0.f;
    float m_r0 = -1e30f, m_r1 = -1e30f, l_r0 = 0.f, l_r1 = 0.f;

    const uint32_t* qrow = Qs + (wid * 16 + gr) * 68;
    const int srcA = (lane & ~3) | (qd >> 1);
    const int srcB = srcA + 2;
    const bool odd = (qd & 1);

    __syncthreads();

    for (int k0 = 0; k0 < L_; k0 += 64) {
        // Load K (stride 68) and V (stride 72) tiles, tf32
        {
            const int rr = tid >> 2;
            const int cc = (tid & 3) * 16;
            #pragma unroll
            for (int u = 0; u < 4; u++) {
                const float4 kv = *(const float4*)&kbase[(size_t)(k0 + rr) * HD_ + cc + u * 4];
                const float4 vv = *(const float4*)&vbase[(size_t)(k0 + rr) * HD_ + cc + u * 4];
                uint4 tk, tv;
                tk.x = f2tf(kv.x); tk.y = f2tf(kv.y); tk.z = f2tf(kv.z); tk.w = f2tf(kv.w);
                tv.x = f2tf(vv.x); tv.y = f2tf(vv.y); tv.z = f2tf(vv.z); tv.w = f2tf(vv.w);
                *(uint4*)(Ks + rr * 68 + cc + u * 4) = tk;
                *(uint4*)(Vs + rr * 72 + cc + u * 4) = tv;
            }
        }
        if (tid < 64) msk[tid] = mask[b * L_ + k0 + tid];
        __syncthreads();

        // ---- S = Q*K^T (scale folded into Q); warp covers 16 rows x 64 keys
        float sacc[8][4];
        #pragma unroll
        for (int a = 0; a < 8; a++)
            #pragma unroll
            for (int c = 0; c < 4; c++) sacc[a][c] = 0.f;

        #pragma unroll
        for (int g = 0; g < 8; g++) {
            uint32_t af[4];
            const uint32_t* p = qrow + g * 8 + qd;
            af[0] = p[0]; af[1] = p[8 * 68]; af[2] = p[4]; af[3] = p[8 * 68 + 4];
            #pragma unroll
            for (int nt = 0; nt < 8; nt++) {
                uint32_t bf[2];
                const uint32_t* kp = Ks + (nt * 8 + gr) * 68 + g * 8 + qd;
                bf[0] = kp[0]; bf[1] = kp[4];
                mma8(sacc[nt], af, bf);
            }
        }

        // ---- mask + online softmax, fully in registers
        #pragma unroll
        for (int nt = 0; nt < 8; nt++) {
            if (!msk[8 * nt + 2 * qd])     { sacc[nt][0] = -1e30f; sacc[nt][2] = -1e30f; }
            if (!msk[8 * nt + 2 * qd + 1]) { sacc[nt][1] = -1e30f; sacc[nt][3] = -1e30f; }
        }
        float rm0 = m_r0, rm1 = m_r1;
        #pragma unroll
        for (int nt = 0; nt < 8; nt++) {
            rm0 = fmaxf(rm0, fmaxf(sacc[nt][0], sacc[nt][1]));
            rm1 = fmaxf(rm1, fmaxf(sacc[nt][2], sacc[nt][3]));
        }
        rm0 = fmaxf(rm0, __shfl_xor_sync(0xFFFFFFFF, rm0, 1));
        rm0 = fmaxf(rm0, __shfl_xor_sync(0xFFFFFFFF, rm0, 2));
        rm1 = fmaxf(rm1, __shfl_xor_sync(0xFFFFFFFF, rm1, 1));
        rm1 = fmaxf(rm1, __shfl_xor_sync(0xFFFFFFFF, rm1, 2));

        const float corr0 = __expf(m_r0 - rm0);
        const float corr1 = __expf(m_r1 - rm1);
        float ls0 = 0.f, ls1 = 0.f;
        #pragma unroll
        for (int nt = 0; nt < 8; nt++) {
            sacc[nt][0] = (sacc[nt][0] < -1e29f) ? 0.f : __expf(sacc[nt][0] - rm0);
            sacc[nt][1] = (sacc[nt][1] < -1e29f) ? 0.f : __expf(sacc[nt][1] - rm0);
            sacc[nt][2] = (sacc[nt][2] < -1e29f) ? 0.f : __expf(sacc[nt][2] - rm1);
            sacc[nt][3] = (sacc[nt][3] < -1e29f) ? 0.f : __expf(sacc[nt][3] - rm1);
            ls0 += sacc[nt][0] + sacc[nt][1];
            ls1 += sacc[nt][2] + sacc[nt][3];
        }
        ls0 += __shfl_xor_sync(0xFFFFFFFF, ls0, 1);
        ls0 += __shfl_xor_sync(0xFFFFFFFF, ls0, 2);
        ls1 += __shfl_xor_sync(0xFFFFFFFF, ls1, 1);
        ls1 += __shfl_xor_sync(0xFFFFFFFF, ls1, 2);

        m_r0 = rm0; m_r1 = rm1;
        l_r0 = l_r0 * corr0 + ls0;
        l_r1 = l_r1 * corr1 + ls1;

        #pragma unroll
        for (int nt = 0; nt < 8; nt++) {
            accO[nt][0] *= corr0; accO[nt][1] *= corr0;
            accO[nt][2] *= corr1; accO[nt][3] *= corr1;
        }

        // ---- P (C-frag) -> A-frag via quad shuffles, then O += P @ V
        #pragma unroll
        for (int g = 0; g < 8; g++) {
            const float v0 = __shfl_sync(0xFFFFFFFF, sacc[g][0], srcA);
            const float v1 = __shfl_sync(0xFFFFFFFF, sacc[g][1], srcA);
            const float v2 = __shfl_sync(0xFFFFFFFF, sacc[g][2], srcA);
            const float v3 = __shfl_sync(0xFFFFFFFF, sacc[g][3], srcA);
            const float w0 = __shfl_sync(0xFFFFFFFF, sacc[g][0], srcB);
            const float w1 = __shfl_sync(0xFFFFFFFF, sacc[g][1], srcB);
            const float w2 = __shfl_sync(0xFFFFFFFF, sacc[g][2], srcB);
            const float w3 = __shfl_sync(0xFFFFFFFF, sacc[g][3], srcB);
            uint32_t pa[4];
            pa[0] = f2tf(odd ? v1 : v0);
            pa[1] = f2tf(odd ? v3 : v2);
            pa[2] = f2tf(odd ? w1 : w0);
            pa[3] = f2tf(odd ? w3 : w2);
            #pragma unroll
            for (int nt = 0; nt < 8; nt++) {
                uint32_t bf[2];
                const uint32_t* vp = Vs + (g * 8 + qd) * 72 + nt * 8 + gr;
                bf[0] = vp[0]; bf[1] = vp[4 * 72];
                mma8(accO[nt], pa, bf);
            }
        }
        __syncthreads();
    }

    // ---- normalize + write ctx (combined-head layout)
    {
        const float i0 = (l_r0 > 0.f) ? 1.f / l_r0 : 0.f;
        const float i1 = (l_r1 > 0.f) ? 1.f / l_r1 : 0.f;
        const int row0 = q0 + wid * 16 + gr;
        #pragma unroll
        for (int nt = 0; nt < 8; nt++) {
            const int n = h * HD_ + nt * 8 + qd * 2;
            float2 o0, o1;
            o0.x = accO[nt][0] * i0; o0.y = accO[nt][1] * i0;
            o1.x = accO[nt][2] * i1; o1.y = accO[nt][3] * i1;
            *(float2*)&ctx[((size_t)(b * L_ + row0)) * D_ + n] = o0;
            *(float2*)&ctx[((size_t)(b * L_ + row0 + 8)) * D_ + n] = o1;
        }
    }
}

// ---------------------------------------------------------------------------
extern "C" void kernel_launch(void* const* d_in, const int* in_sizes, int n_in,
                              void* d_out, int out_size)
{
    const float* query = (const float*)d_in[0];
    const float* key_  = (const float*)d_in[1];
    const float* value = (const float*)d_in[2];
    const int*   mask  = (const int*)  d_in[3];
    const float* Wq    = (const float*)d_in[4];
    const float* Wk    = (const float*)d_in[5];
    const float* Wv    = (const float*)d_in[6];
    const float* Wo    = (const float*)d_in[7];
    const float* bo    = (const float*)d_in[8];
    float* out = (float*)d_out;

    float *pq, *pk, *pv, *pc;
    cudaGetSymbolAddress((void**)&pq, g_q);
    cudaGetSymbolAddress((void**)&pk, g_k);
    cudaGetSymbolAddress((void**)&pv, g_v);
    cudaGetSymbolAddress((void**)&pc, g_ctx);

    cudaFuncSetAttribute(gemm_tc<true,  false>,
                         cudaFuncAttributeMaxDynamicSharedMemorySize, GEMM_SMEM);
    cudaFuncSetAttribute(gemm_tc<false, true>,
                         cudaFuncAttributeMaxDynamicSharedMemorySize, GEMM_SMEM);
    cudaFuncSetAttribute(flash_attn,
                         cudaFuncAttributeMaxDynamicSharedMemorySize, FA_SMEM);

    const dim3 gg(D_ / 128, M_ / 128);   // (8, 32)

    gemm_tc<true,  false><<<gg, 256, GEMM_SMEM>>>(query, Wq, nullptr, pq);
    gemm_tc<true,  false><<<gg, 256, GEMM_SMEM>>>(key_,  Wk, nullptr, pk);
    gemm_tc<true,  false><<<gg, 256, GEMM_SMEM>>>(value, Wv, nullptr, pv);

    flash_attn<<<dim3(B_ * H_, L_ / 128), 256, FA_SMEM>>>(pq, pk, pv, mask, pc);

    gemm_tc<false, true><<<gg, 256, GEMM_SMEM>>>(pc, Wo, bo, out);
}